// round 9
// baseline (speedup 1.0000x reference)
#include <cuda_runtime.h>
#include <math.h>

// StatisticalFeatureExtractor: (B=64, C=16, T=65536) fp32 -> (B, C, 17) fp32
// One CTA (512 thr) per row.
//   pass 1 (HBM): raw S1..S4, sum|x|, sum sqrt|x|, min, max, zero-crossings
//   pass 2 (L2):  mean-crossings only (centered moments derived algebraically)
// Hot loops branch-free; cross-chunk sign pairs via shfl_down; warp-span
// boundary pairs in a one-shot cleanup. unroll 8 for MLP.

#define TLEN    65536
#define CHUNKS  (TLEN / 4)
#define THREADS 512
#define NWARP   (THREADS / 32)
#define EPSV    1e-8

typedef unsigned long long u64;

__device__ __forceinline__ u64 pk2(float x, float y) {
    u64 r; asm("mov.b64 %0, {%1, %2};" : "=l"(r) : "f"(x), "f"(y)); return r;
}
__device__ __forceinline__ void up2(u64 a, float& x, float& y) {
    asm("mov.b64 {%0, %1}, %2;" : "=f"(x), "=f"(y) : "l"(a));
}
__device__ __forceinline__ u64 add2(u64 a, u64 b) {
    u64 r; asm("add.rn.f32x2 %0, %1, %2;" : "=l"(r) : "l"(a), "l"(b)); return r;
}
__device__ __forceinline__ u64 mul2(u64 a, u64 b) {
    u64 r; asm("mul.rn.f32x2 %0, %1, %2;" : "=l"(r) : "l"(a), "l"(b)); return r;
}
__device__ __forceinline__ u64 fma2(u64 a, u64 b, u64 c) {
    u64 r; asm("fma.rn.f32x2 %0, %1, %2, %3;" : "=l"(r) : "l"(a), "l"(b), "l"(c)); return r;
}
__device__ __forceinline__ float sqrt_approx(float v) {
    float r; asm("sqrt.approx.f32 %0, %1;" : "=f"(r) : "f"(v)); return r;
}
__device__ __forceinline__ float hsum2(u64 a) { float x, y; up2(a, x, y); return x + y; }

__device__ __forceinline__ float warp_sum(float v) {
#pragma unroll
    for (int o = 16; o; o >>= 1) v += __shfl_xor_sync(0xffffffffu, v, o);
    return v;
}
__device__ __forceinline__ int warp_sumi(int v) {
#pragma unroll
    for (int o = 16; o; o >>= 1) v += __shfl_xor_sync(0xffffffffu, v, o);
    return v;
}
__device__ __forceinline__ float warp_max(float v) {
#pragma unroll
    for (int o = 16; o; o >>= 1) v = fmaxf(v, __shfl_xor_sync(0xffffffffu, v, o));
    return v;
}
__device__ __forceinline__ float warp_min(float v) {
#pragma unroll
    for (int o = 16; o; o >>= 1) v = fminf(v, __shfl_xor_sync(0xffffffffu, v, o));
    return v;
}

__global__ __launch_bounds__(THREADS, 2)
void stat_feat_kernel(const float* __restrict__ x, float* __restrict__ out) {
    const int row = blockIdx.x;
    const float* __restrict__ xr = x + (size_t)row * TLEN;
    const float4* __restrict__ x4 = reinterpret_cast<const float4*>(xr);

    const int tid  = threadIdx.x;
    const int wid  = tid >> 5;
    const int lane = tid & 31;
    const unsigned vmask = (lane != 31) ? 1u : 0u;

    __shared__ float w_s1[NWARP], w_s2[NWARP], w_s3[NWARP], w_s4[NWARP];
    __shared__ float w_sa[NWARP], w_sq[NWARP], w_mx[NWARP], w_mn[NWARP];
    __shared__ int   w_zc[NWARP], w_mc[NWARP], w_ze[NWARP];
    __shared__ double sd[6];          // S1,S2,S3,S4,Sa,Sq
    __shared__ float  sf[2];          // max, min
    __shared__ int    s_zc;
    __shared__ float  s_mean;

    const u64 ABSM = 0x7fffffff7fffffffULL;

    // ---------------- pass 1: raw sums (HBM stream), branch-free ----------------
    u64 s1p = 0, s2p = 0, s3p = 0, s4p = 0, sap = 0;
    float sq0 = 0.f, sq1 = 0.f;
    float mx = -INFINITY, mn = INFINITY;
    int zc = 0;

#pragma unroll 8
    for (int k = tid; k < CHUNKS; k += THREADS) {
        float4 v = x4[k];
        u64 plo = pk2(v.x, v.y), phi = pk2(v.z, v.w);
        u64 tlo = mul2(plo, plo), thi = mul2(phi, phi);

        s1p = add2(s1p, add2(plo, phi));
        s2p = add2(s2p, add2(tlo, thi));
        s3p = fma2(tlo, plo, s3p);
        s3p = fma2(thi, phi, s3p);
        s4p = fma2(tlo, tlo, s4p);
        s4p = fma2(thi, thi, s4p);

        u64 alo = plo & ABSM, ahi = phi & ABSM;
        sap = add2(sap, add2(alo, ahi));

        float b0, b1, b2, b3;
        up2(alo, b0, b1); up2(ahi, b2, b3);
        sq0 += sqrt_approx(b0) + sqrt_approx(b1);
        sq1 += sqrt_approx(b2) + sqrt_approx(b3);

        mx = fmaxf(mx, fmaxf(fmaxf(v.x, v.y), fmaxf(v.z, v.w)));
        mn = fminf(mn, fminf(fminf(v.x, v.y), fminf(v.z, v.w)));

        unsigned u0 = __float_as_uint(v.x), u1 = __float_as_uint(v.y);
        unsigned u2 = __float_as_uint(v.z), u3 = __float_as_uint(v.w);
        unsigned nu0 = __shfl_down_sync(0xffffffffu, u0, 1);
        zc += (int)(((u0 ^ u1) >> 31) + ((u1 ^ u2) >> 31) + ((u2 ^ u3) >> 31)
                    + (((u3 ^ nu0) >> 31) & vmask));
    }

    {
        float s1 = hsum2(s1p), s2 = hsum2(s2p), s3 = hsum2(s3p);
        float s4 = hsum2(s4p), sa = hsum2(sap), sqv = sq0 + sq1;
        s1 = warp_sum(s1); s2 = warp_sum(s2); s3 = warp_sum(s3);
        s4 = warp_sum(s4); sa = warp_sum(sa); sqv = warp_sum(sqv);
        mx = warp_max(mx); mn = warp_min(mn); zc = warp_sumi(zc);
        if (lane == 0) {
            w_s1[wid] = s1; w_s2[wid] = s2; w_s3[wid] = s3; w_s4[wid] = s4;
            w_sa[wid] = sa; w_sq[wid] = sqv; w_mx[wid] = mx; w_mn[wid] = mn;
            w_zc[wid] = zc;
        }
    }
    __syncthreads();
    if (tid == 0) {
        double S1 = 0, S2 = 0, S3 = 0, S4 = 0, Sa = 0, Sq = 0;
        float rmx = -INFINITY, rmn = INFINITY;
        int rzc = 0;
        for (int i = 0; i < NWARP; i++) {
            S1 += (double)w_s1[i]; S2 += (double)w_s2[i];
            S3 += (double)w_s3[i]; S4 += (double)w_s4[i];
            Sa += (double)w_sa[i]; Sq += (double)w_sq[i];
            rmx = fmaxf(rmx, w_mx[i]); rmn = fminf(rmn, w_mn[i]);
            rzc += w_zc[i];
        }
        sd[0] = S1; sd[1] = S2; sd[2] = S3; sd[3] = S4; sd[4] = Sa; sd[5] = Sq;
        sf[0] = rmx; sf[1] = rmn; s_zc = rzc;
        s_mean = (float)(S1 * (1.0 / (double)TLEN));
    }
    __syncthreads();

    const float mean = s_mean;
    const u64 nm2 = pk2(-mean, -mean);

    // ---------------- pass 2: mean crossings only (L2 re-read), branch-free ----------------
    int mc = 0;

#pragma unroll 8
    for (int k = tid; k < CHUNKS; k += THREADS) {
        float4 v = x4[k];
        u64 dlo = add2(pk2(v.x, v.y), nm2), dhi = add2(pk2(v.z, v.w), nm2);
        float d0, d1, d2v, d3v;
        up2(dlo, d0, d1); up2(dhi, d2v, d3v);
        unsigned u0 = __float_as_uint(d0), u1 = __float_as_uint(d1);
        unsigned u2 = __float_as_uint(d2v), u3 = __float_as_uint(d3v);
        unsigned nu0 = __shfl_down_sync(0xffffffffu, u0, 1);
        mc += (int)(((u0 ^ u1) >> 31) + ((u1 ^ u2) >> 31) + ((u2 ^ u3) >> 31)
                    + (((u3 ^ nu0) >> 31) & vmask));
    }

    // ---------------- cleanup: 511 warp-span boundary pairs (zcr & mcr) ----------------
    int zce = 0;
    if (tid < 511) {
        float a = __ldg(xr + 128 * tid + 127);
        float b = __ldg(xr + 128 * tid + 128);
        zce = (int)((__float_as_uint(a) ^ __float_as_uint(b)) >> 31);
        float ca = a - mean, cb = b - mean;
        mc += (int)((__float_as_uint(ca) ^ __float_as_uint(cb)) >> 31);
    }

    mc = warp_sumi(mc); zce = warp_sumi(zce);
    if (lane == 0) { w_mc[wid] = mc; w_ze[wid] = zce; }
    __syncthreads();

    if (tid == 0) {
        int rmc = 0, rzce = 0;
        for (int i = 0; i < NWARP; i++) { rmc += w_mc[i]; rzce += w_ze[i]; }

        const double Td   = (double)TLEN;
        const double invT = 1.0 / Td;
        double S1 = sd[0], S2 = sd[1], S3 = sd[2], S4 = sd[3], Sa = sd[4], Sq = sd[5];
        double pk = sf[0], pkn = sf[1];
        int    zct = s_zc + rzce;

        double m       = S1 * invT;
        double m2      = S2 * invT;
        double varc    = (S2 - S1 * m) / (Td - 1.0);
        double stdv    = sqrt(varc);
        double rms     = sqrt(m2);
        double ptp     = pk - pkn;
        double abs_peak = fabs(pk);
        double crest   = abs_peak / (rms + EPSV);
        double mean_abs = Sa * invT;
        double shape   = rms / (mean_abs + EPSV);
        double impulse = abs_peak / (mean_abs + EPSV);
        double sqrt_mean = Sq * invT;
        double clearance = abs_peak / (sqrt_mean * sqrt_mean + EPSV);
        double m3      = S3 * invT;
        double m4      = S4 * invT;
        double m3c     = m3 - 3.0 * m * m2 + 2.0 * m * m * m;
        double m4c     = m4 - 4.0 * m * m3 + 6.0 * m * m * m2 - 3.0 * m * m * m * m;
        double skew    = m3c / (stdv * stdv * stdv + EPSV);
        double kurt    = m4c / (varc * varc + EPSV) - 3.0;
        double zcr     = (double)zct / (Td - 1.0);
        double mcr     = (double)rmc / (Td - 1.0);
        double margin  = abs_peak / (sqrt_mean + EPSV);
        double energy  = S2;

        float* o = out + (size_t)row * 17;
        o[0]  = (float)m;
        o[1]  = (float)stdv;
        o[2]  = (float)varc;
        o[3]  = (float)rms;
        o[4]  = (float)pk;
        o[5]  = (float)pkn;
        o[6]  = (float)ptp;
        o[7]  = (float)crest;
        o[8]  = (float)shape;
        o[9]  = (float)impulse;
        o[10] = (float)clearance;
        o[11] = (float)skew;
        o[12] = (float)kurt;
        o[13] = (float)zcr;
        o[14] = (float)mcr;
        o[15] = (float)margin;
        o[16] = (float)energy;
    }
}

extern "C" void kernel_launch(void* const* d_in, const int* in_sizes, int n_in,
                              void* d_out, int out_size) {
    const float* x = (const float*)d_in[0];
    float* out = (float*)d_out;
    int rows = in_sizes[0] / TLEN;   // 64*16 = 1024
    stat_feat_kernel<<<rows, THREADS>>>(x, out);
}